// round 1
// baseline (speedup 1.0000x reference)
#include <cuda_runtime.h>
#include <math.h>

#define NN 50000
#define NE 800000
#define DEPTH 4

// ---------------- scratch (static device globals; no allocation) ----------------
__device__ float g_X [NN*64];
__device__ float g_Y1[NN*64];
__device__ float g_Y2[NN*64];
__device__ float g_Xn[NN*64];
__device__ float g_XG[NN*64];
__device__ float g_dis[NN];
__device__ int g_cnt_dst[NN];
__device__ int g_cnt_src[NN];
__device__ int g_rp_dst[NN+1];
__device__ int g_rp_src[NN+1];
__device__ int g_off_dst[NN];
__device__ int g_off_src[NN];
__device__ int g_col_src[NE];   // CSR by dst: source node of each in-edge
__device__ int g_col_dst[NE];   // CSR by src: dest node of each out-edge

// ---------------- graph preprocessing ----------------
__global__ void k_zero_counts() {
    int i = blockIdx.x * blockDim.x + threadIdx.x;
    if (i < NN) { g_cnt_dst[i] = 0; g_cnt_src[i] = 0; }
}

__global__ void k_count(const int* __restrict__ ei) {
    int i = blockIdx.x * blockDim.x + threadIdx.x;
    if (i < NE) {
        int s = ei[i], d = ei[NE + i];
        atomicAdd(&g_cnt_dst[d], 1);
        atomicAdd(&g_cnt_src[s], 1);
    }
}

__device__ void scan_phase(const int* __restrict__ cnt, int* __restrict__ rp,
                           int* __restrict__ off, bool dodis, int* part) {
    int t = threadIdx.x;
    const int CH = (NN + 1023) / 1024;
    int b = t * CH;
    int e = b + CH; if (e > NN) e = NN; if (b > NN) b = NN;
    int s = 0;
    for (int i = b; i < e; i++) s += cnt[i];
    part[t] = s;
    __syncthreads();
    for (int o = 1; o < 1024; o <<= 1) {
        int v = (t >= o) ? part[t - o] : 0;
        __syncthreads();
        part[t] += v;
        __syncthreads();
    }
    int run = (t > 0) ? part[t - 1] : 0;
    for (int i = b; i < e; i++) {
        rp[i] = run; off[i] = run; run += cnt[i];
        if (dodis) g_dis[i] = rsqrtf((float)cnt[i] + 1.0f);
    }
    if (t == 1023) rp[NN] = part[1023];
}

__global__ void k_scan_both() {
    __shared__ int part[1024];
    scan_phase(g_cnt_dst, g_rp_dst, g_off_dst, true, part);
    __syncthreads();
    scan_phase(g_cnt_src, g_rp_src, g_off_src, false, part);
}

__global__ void k_fill(const int* __restrict__ ei) {
    int i = blockIdx.x * blockDim.x + threadIdx.x;
    if (i < NE) {
        int s = ei[i], d = ei[NE + i];
        int p = atomicAdd(&g_off_dst[d], 1); g_col_src[p] = s;
        int q = atomicAdd(&g_off_src[s], 1); g_col_dst[q] = d;
    }
}

// ---------------- GEMM: A[n x K] @ W[K x 64], tile 32 rows x 64 cols ----------------
// RELU_BIAS: O1 = relu(A@W1 + b)           (encoder / decoder)
// !RELU_BIAS: O1 = dis[r]*(A@W1), O2 = dis[r]*(A@W2)   (pre-scaled conv inputs)
template<int K, bool DUAL, bool RELU_BIAS>
__global__ void __launch_bounds__(128) gemm_k(
    const float* __restrict__ A,
    const float* __restrict__ W1,
    const float* __restrict__ W2,
    const float* __restrict__ bias,
    float* __restrict__ O1,
    float* __restrict__ O2)
{
    __shared__ float As[32][65];
    __shared__ float Ws1[64 * 64];
    __shared__ float Ws2[64 * 64];

    int tid = threadIdx.x;            // 128 threads
    int tx = tid & 15;                // 16 col-groups of 4
    int ty = tid >> 4;                // 8 row-groups of 4
    int rowbase = blockIdx.x * 32;
    int col0 = tx * 4;

    float acc1[4][4] = {};
    float acc2[4][4] = {};

    #pragma unroll
    for (int c = 0; c < K / 64; c++) {
        // A tile: 32 x 64
        #pragma unroll
        for (int i = tid; i < 32 * 16; i += 128) {
            int r = i >> 4, q = i & 15;
            int row = rowbase + r;
            float4 v = make_float4(0.f, 0.f, 0.f, 0.f);
            if (row < NN)
                v = *(const float4*)&A[(size_t)row * K + c * 64 + q * 4];
            As[r][q * 4 + 0] = v.x; As[r][q * 4 + 1] = v.y;
            As[r][q * 4 + 2] = v.z; As[r][q * 4 + 3] = v.w;
        }
        // W tile(s): 64 x 64
        #pragma unroll
        for (int i = tid; i < 64 * 16; i += 128) {
            ((float4*)Ws1)[i] = ((const float4*)(W1 + c * 64 * 64))[i];
            if (DUAL)
                ((float4*)Ws2)[i] = ((const float4*)(W2 + c * 64 * 64))[i];
        }
        __syncthreads();

        #pragma unroll 16
        for (int kk = 0; kk < 64; kk++) {
            float4 w1 = *(const float4*)&Ws1[kk * 64 + col0];
            float av[4];
            #pragma unroll
            for (int i = 0; i < 4; i++) av[i] = As[ty * 4 + i][kk];
            #pragma unroll
            for (int i = 0; i < 4; i++) {
                acc1[i][0] += av[i] * w1.x;
                acc1[i][1] += av[i] * w1.y;
                acc1[i][2] += av[i] * w1.z;
                acc1[i][3] += av[i] * w1.w;
            }
            if (DUAL) {
                float4 w2 = *(const float4*)&Ws2[kk * 64 + col0];
                #pragma unroll
                for (int i = 0; i < 4; i++) {
                    acc2[i][0] += av[i] * w2.x;
                    acc2[i][1] += av[i] * w2.y;
                    acc2[i][2] += av[i] * w2.z;
                    acc2[i][3] += av[i] * w2.w;
                }
            }
        }
        __syncthreads();
    }

    #pragma unroll
    for (int i = 0; i < 4; i++) {
        int row = rowbase + ty * 4 + i;
        if (row >= NN) break;
        if (RELU_BIAS) {
            float4 b = *(const float4*)&bias[col0];
            float4 o;
            o.x = fmaxf(acc1[i][0] + b.x, 0.f);
            o.y = fmaxf(acc1[i][1] + b.y, 0.f);
            o.z = fmaxf(acc1[i][2] + b.z, 0.f);
            o.w = fmaxf(acc1[i][3] + b.w, 0.f);
            *(float4*)&O1[(size_t)row * 64 + col0] = o;
        } else {
            float s = g_dis[row];
            float4 o1, o2;
            o1.x = s * acc1[i][0]; o1.y = s * acc1[i][1];
            o1.z = s * acc1[i][2]; o1.w = s * acc1[i][3];
            o2.x = s * acc2[i][0]; o2.y = s * acc2[i][1];
            o2.z = s * acc2[i][2]; o2.w = s * acc2[i][3];
            *(float4*)&O1[(size_t)row * 64 + col0] = o1;
            *(float4*)&O2[(size_t)row * 64 + col0] = o2;
        }
    }
}

// ---------------- dual aggregation over in-edges (CSR by dst) ----------------
// X_[d] = relu(dis[d]*(y1[d] + sum_in y1[s]) + conv_b)
// XG[d] = relu(dis[d]*(y2[d] + sum_in y2[s]) + gg_b)
__global__ void __launch_bounds__(256) k_agg_dual(
    const float* __restrict__ conv_b, const float* __restrict__ gg_b)
{
    int w = (blockIdx.x * blockDim.x + threadIdx.x) >> 5;
    int lane = threadIdx.x & 31;
    if (w >= NN) return;
    int o = lane * 2;

    float2 a1 = *(const float2*)&g_Y1[(size_t)w * 64 + o];  // self-loop
    float2 a2 = *(const float2*)&g_Y2[(size_t)w * 64 + o];

    int b = g_rp_dst[w], e = g_rp_dst[w + 1];
    for (int j = b; j < e; j++) {
        int s = g_col_src[j];
        float2 v1 = *(const float2*)&g_Y1[(size_t)s * 64 + o];
        float2 v2 = *(const float2*)&g_Y2[(size_t)s * 64 + o];
        a1.x += v1.x; a1.y += v1.y;
        a2.x += v2.x; a2.y += v2.y;
    }
    float d = g_dis[w];
    float2 b1 = *(const float2*)&conv_b[o];
    float2 b2 = *(const float2*)&gg_b[o];
    float2 xn, xg;
    xn.x = fmaxf(d * a1.x + b1.x, 0.f);
    xn.y = fmaxf(d * a1.y + b1.y, 0.f);
    xg.x = fmaxf(d * a2.x + b2.x, 0.f);
    xg.y = fmaxf(d * a2.y + b2.y, 0.f);
    *(float2*)&g_Xn[(size_t)w * 64 + o] = xn;
    *(float2*)&g_XG[(size_t)w * 64 + o] = xg;
}

// ---------------- gate + state update (CSR by src) ----------------
// tau = tanh( sum_out (XG[s]-XG[d])^2 / max(outdeg,1) );  X = X + tau*(X_ - X)
__global__ void __launch_bounds__(256) k_gate()
{
    int w = (blockIdx.x * blockDim.x + threadIdx.x) >> 5;
    int lane = threadIdx.x & 31;
    if (w >= NN) return;
    int o = lane * 2;

    float2 xs = *(const float2*)&g_XG[(size_t)w * 64 + o];
    float sx = 0.f, sy = 0.f;
    int b = g_rp_src[w], e = g_rp_src[w + 1];
    for (int j = b; j < e; j++) {
        int d = g_col_dst[j];
        float2 xd = *(const float2*)&g_XG[(size_t)d * 64 + o];
        float tx = xs.x - xd.x, ty = xs.y - xd.y;
        sx += tx * tx; sy += ty * ty;
    }
    float denom = fmaxf((float)(e - b), 1.f);
    float taux = tanhf(sx / denom);
    float tauy = tanhf(sy / denom);

    float2 xo = *(const float2*)&g_X [(size_t)w * 64 + o];
    float2 xn = *(const float2*)&g_Xn[(size_t)w * 64 + o];
    float2 r;
    r.x = xo.x + taux * (xn.x - xo.x);
    r.y = xo.y + tauy * (xn.y - xo.y);
    *(float2*)&g_X[(size_t)w * 64 + o] = r;
}

// ---------------- launch ----------------
extern "C" void kernel_launch(void* const* d_in, const int* in_sizes, int n_in,
                              void* d_out, int out_size)
{
    const float* x      = (const float*)d_in[0];
    const int*   ei     = (const int*)  d_in[1];
    const float* enc_w  = (const float*)d_in[2];
    const float* enc_b  = (const float*)d_in[3];
    const float* conv_w = (const float*)d_in[4];
    const float* conv_b = (const float*)d_in[5];
    const float* gg_w   = (const float*)d_in[6];
    const float* gg_b   = (const float*)d_in[7];
    const float* dec_w  = (const float*)d_in[8];
    const float* dec_b  = (const float*)d_in[9];
    float* out = (float*)d_out;

    float *pX, *pY1, *pY2;
    cudaGetSymbolAddress((void**)&pX,  g_X);
    cudaGetSymbolAddress((void**)&pY1, g_Y1);
    cudaGetSymbolAddress((void**)&pY2, g_Y2);

    // graph preprocessing (per-launch; deterministic)
    k_zero_counts<<<(NN + 255) / 256, 256>>>();
    k_count<<<(NE + 255) / 256, 256>>>(ei);
    k_scan_both<<<1, 1024>>>();
    k_fill<<<(NE + 255) / 256, 256>>>(ei);

    const int GEMM_BLOCKS = (NN + 31) / 32;
    const int NODE_BLOCKS = (NN * 32 + 255) / 256;

    // encoder: X = relu(x @ enc_w + enc_b)
    gemm_k<256, false, true><<<GEMM_BLOCKS, 128>>>(x, enc_w, nullptr, enc_b, pX, nullptr);

    for (int it = 0; it < DEPTH; it++) {
        // y1 = dis * (X @ conv_w), y2 = dis * (X @ gg_w)
        gemm_k<64, true, false><<<GEMM_BLOCKS, 128>>>(pX, conv_w, gg_w, nullptr, pY1, pY2);
        // X_ and XG via shared CSR walk
        k_agg_dual<<<NODE_BLOCKS, 256>>>(conv_b, gg_b);
        // tau + state update
        k_gate<<<NODE_BLOCKS, 256>>>();
    }

    // decoder: out = relu(X @ dec_w + dec_b)
    gemm_k<64, false, true><<<GEMM_BLOCKS, 128>>>(pX, dec_w, nullptr, dec_b, out, nullptr);
}

// round 2
// speedup vs baseline: 1.0843x; 1.0843x over previous
#include <cuda_runtime.h>
#include <math.h>

#define NN 50000
#define NE 800000
#define DEPTH 4

// ---------------- scratch (static device globals; no allocation) ----------------
__device__ float g_X [NN*64];   // node state
__device__ float g_Xd[NN*64];   // dis[i] * X[i]  (pre-scaled for aggregation)
__device__ float g_A [NN*64];   // aggregated features (shared by both convs)
__device__ float g_Xn[NN*64];   // relu(conv(X))
__device__ float g_XG[NN*64];   // relu(gate-conv(X))
__device__ float g_dis[NN];
__device__ int g_cnt_dst[NN];
__device__ int g_cnt_src[NN];
__device__ int g_rp_dst[NN+1];
__device__ int g_rp_src[NN+1];
__device__ int g_off_dst[NN];
__device__ int g_off_src[NN];
__device__ int g_col_src[NE];   // CSR by dst: source node of each in-edge
__device__ int g_col_dst[NE];   // CSR by src: dest node of each out-edge

// ---------------- graph preprocessing ----------------
__global__ void k_zero_counts() {
    int i = blockIdx.x * blockDim.x + threadIdx.x;
    if (i < NN) { g_cnt_dst[i] = 0; g_cnt_src[i] = 0; }
}

__global__ void k_count(const int* __restrict__ ei) {
    int i = blockIdx.x * blockDim.x + threadIdx.x;
    if (i < NE) {
        int s = ei[i], d = ei[NE + i];
        atomicAdd(&g_cnt_dst[d], 1);
        atomicAdd(&g_cnt_src[s], 1);
    }
}

__device__ void scan_phase(const int* __restrict__ cnt, int* __restrict__ rp,
                           int* __restrict__ off, bool dodis, int* part) {
    int t = threadIdx.x;
    const int CH = (NN + 1023) / 1024;
    int b = t * CH;
    int e = b + CH; if (e > NN) e = NN; if (b > NN) b = NN;
    int s = 0;
    for (int i = b; i < e; i++) s += cnt[i];
    part[t] = s;
    __syncthreads();
    for (int o = 1; o < 1024; o <<= 1) {
        int v = (t >= o) ? part[t - o] : 0;
        __syncthreads();
        part[t] += v;
        __syncthreads();
    }
    int run = (t > 0) ? part[t - 1] : 0;
    for (int i = b; i < e; i++) {
        rp[i] = run; off[i] = run; run += cnt[i];
        if (dodis) g_dis[i] = rsqrtf((float)cnt[i] + 1.0f);
    }
    if (t == 1023) rp[NN] = part[1023];
}

__global__ void k_scan_both() {
    __shared__ int part[1024];
    scan_phase(g_cnt_dst, g_rp_dst, g_off_dst, true, part);
    __syncthreads();
    scan_phase(g_cnt_src, g_rp_src, g_off_src, false, part);
}

__global__ void k_fill(const int* __restrict__ ei) {
    int i = blockIdx.x * blockDim.x + threadIdx.x;
    if (i < NE) {
        int s = ei[i], d = ei[NE + i];
        int p = atomicAdd(&g_off_dst[d], 1); g_col_src[p] = s;
        int q = atomicAdd(&g_off_src[s], 1); g_col_dst[q] = d;
    }
}

// ---------------- GEMM: A[n x K] @ W[K x 64], tile 32 rows x 64 cols ----------------
// O1 = relu(A@W1 + b1);  if DUAL: O2 = relu(A@W2 + b2);
// if WRITE_SCALED: Os = dis[row] * O1
template<int K, bool DUAL, bool WRITE_SCALED>
__global__ void __launch_bounds__(128) gemm_k(
    const float* __restrict__ A,
    const float* __restrict__ W1,
    const float* __restrict__ W2,
    const float* __restrict__ b1,
    const float* __restrict__ b2,
    float* __restrict__ O1,
    float* __restrict__ O2,
    float* __restrict__ Os)
{
    __shared__ float AsT[64][36];               // transposed A tile: [k][row], 16B-aligned rows
    constexpr int NW = DUAL ? 2 : 1;
    __shared__ float Ws[NW * 64 * 64];

    int tid = threadIdx.x;            // 128 threads
    int tx = tid & 15;                // 16 col-groups of 4
    int ty = tid >> 4;                // 8 row-groups of 4
    int rowbase = blockIdx.x * 32;
    int col0 = tx * 4;

    float acc1[4][4] = {};
    float acc2[4][4] = {};

    #pragma unroll
    for (int c = 0; c < K / 64; c++) {
        // A tile: 32 rows x 64 cols, stored transposed
        #pragma unroll
        for (int it = 0; it < 4; it++) {
            int i = tid + it * 128;
            int r = i >> 4, q = i & 15;
            int row = rowbase + r;
            float4 v = make_float4(0.f, 0.f, 0.f, 0.f);
            if (row < NN)
                v = *(const float4*)&A[(size_t)row * K + c * 64 + q * 4];
            AsT[q * 4 + 0][r] = v.x; AsT[q * 4 + 1][r] = v.y;
            AsT[q * 4 + 2][r] = v.z; AsT[q * 4 + 3][r] = v.w;
        }
        // W tile(s): 64 x 64
        #pragma unroll
        for (int i = tid; i < NW * 64 * 16; i += 128)
            ((float4*)Ws)[i] = ((const float4*)(W1 + c * 64 * 64))[0], // placeholder overwritten below
            ((float4*)Ws)[i] = (i < 64 * 16)
                ? ((const float4*)(W1 + c * 64 * 64))[i]
                : ((const float4*)(W2 + c * 64 * 64))[i - 64 * 16];
        __syncthreads();

        #pragma unroll 16
        for (int kk = 0; kk < 64; kk++) {
            float4 av = *(const float4*)&AsT[kk][ty * 4];
            float4 w1 = *(const float4*)&Ws[kk * 64 + col0];
            float a[4] = {av.x, av.y, av.z, av.w};
            #pragma unroll
            for (int i = 0; i < 4; i++) {
                acc1[i][0] += a[i] * w1.x;
                acc1[i][1] += a[i] * w1.y;
                acc1[i][2] += a[i] * w1.z;
                acc1[i][3] += a[i] * w1.w;
            }
            if (DUAL) {
                float4 w2 = *(const float4*)&Ws[64 * 64 + kk * 64 + col0];
                #pragma unroll
                for (int i = 0; i < 4; i++) {
                    acc2[i][0] += a[i] * w2.x;
                    acc2[i][1] += a[i] * w2.y;
                    acc2[i][2] += a[i] * w2.z;
                    acc2[i][3] += a[i] * w2.w;
                }
            }
        }
        __syncthreads();
    }

    float4 bb1 = *(const float4*)&b1[col0];
    float4 bb2 = DUAL ? *(const float4*)&b2[col0] : make_float4(0.f, 0.f, 0.f, 0.f);

    #pragma unroll
    for (int i = 0; i < 4; i++) {
        int row = rowbase + ty * 4 + i;
        if (row >= NN) break;
        float4 o;
        o.x = fmaxf(acc1[i][0] + bb1.x, 0.f);
        o.y = fmaxf(acc1[i][1] + bb1.y, 0.f);
        o.z = fmaxf(acc1[i][2] + bb1.z, 0.f);
        o.w = fmaxf(acc1[i][3] + bb1.w, 0.f);
        *(float4*)&O1[(size_t)row * 64 + col0] = o;
        if (WRITE_SCALED) {
            float s = g_dis[row];
            float4 os = make_float4(s * o.x, s * o.y, s * o.z, s * o.w);
            *(float4*)&Os[(size_t)row * 64 + col0] = os;
        }
        if (DUAL) {
            float4 o2;
            o2.x = fmaxf(acc2[i][0] + bb2.x, 0.f);
            o2.y = fmaxf(acc2[i][1] + bb2.y, 0.f);
            o2.z = fmaxf(acc2[i][2] + bb2.z, 0.f);
            o2.w = fmaxf(acc2[i][3] + bb2.w, 0.f);
            *(float4*)&O2[(size_t)row * 64 + col0] = o2;
        }
    }
}

// ---------------- shared aggregation over in-edges (CSR by dst) ----------------
// A[d] = dis[d] * ( Xd[d] + sum_{s->d} Xd[s] ),  Xd[i] = dis[i]*X[i]
// 16 lanes per node, float4 per lane (64 floats = 256B per row)
__global__ void __launch_bounds__(256) k_agg()
{
    int g = (blockIdx.x * blockDim.x + threadIdx.x) >> 4;
    int l = threadIdx.x & 15;
    if (g >= NN) return;
    int o = l * 4;

    float4 a = *(const float4*)&g_Xd[(size_t)g * 64 + o];  // self-loop term
    int b = g_rp_dst[g], e = g_rp_dst[g + 1];
    for (int j = b; j < e; j++) {
        int s = g_col_src[j];
        float4 v = *(const float4*)&g_Xd[(size_t)s * 64 + o];
        a.x += v.x; a.y += v.y; a.z += v.z; a.w += v.w;
    }
    float d = g_dis[g];
    float4 r = make_float4(d * a.x, d * a.y, d * a.z, d * a.w);
    *(float4*)&g_A[(size_t)g * 64 + o] = r;
}

// ---------------- gate + state update (CSR by src) ----------------
// tau = tanh( sum_out (XG[s]-XG[d])^2 / max(outdeg,1) )
// X = X + tau*(Xn - X);  Xd = dis*X
__global__ void __launch_bounds__(256) k_gate()
{
    int g = (blockIdx.x * blockDim.x + threadIdx.x) >> 4;
    int l = threadIdx.x & 15;
    if (g >= NN) return;
    int o = l * 4;

    float4 xs = *(const float4*)&g_XG[(size_t)g * 64 + o];
    float4 s = make_float4(0.f, 0.f, 0.f, 0.f);
    int b = g_rp_src[g], e = g_rp_src[g + 1];
    for (int j = b; j < e; j++) {
        int d = g_col_dst[j];
        float4 xd = *(const float4*)&g_XG[(size_t)d * 64 + o];
        float tx = xs.x - xd.x, ty = xs.y - xd.y;
        float tz = xs.z - xd.z, tw = xs.w - xd.w;
        s.x += tx * tx; s.y += ty * ty;
        s.z += tz * tz; s.w += tw * tw;
    }
    float inv = 1.0f / fmaxf((float)(e - b), 1.f);
    float4 tau;
    tau.x = tanhf(s.x * inv); tau.y = tanhf(s.y * inv);
    tau.z = tanhf(s.z * inv); tau.w = tanhf(s.w * inv);

    float4 xo = *(const float4*)&g_X [(size_t)g * 64 + o];
    float4 xn = *(const float4*)&g_Xn[(size_t)g * 64 + o];
    float4 r;
    r.x = xo.x + tau.x * (xn.x - xo.x);
    r.y = xo.y + tau.y * (xn.y - xo.y);
    r.z = xo.z + tau.z * (xn.z - xo.z);
    r.w = xo.w + tau.w * (xn.w - xo.w);
    *(float4*)&g_X[(size_t)g * 64 + o] = r;
    float di = g_dis[g];
    float4 rd = make_float4(di * r.x, di * r.y, di * r.z, di * r.w);
    *(float4*)&g_Xd[(size_t)g * 64 + o] = rd;
}

// ---------------- launch ----------------
extern "C" void kernel_launch(void* const* d_in, const int* in_sizes, int n_in,
                              void* d_out, int out_size)
{
    const float* x      = (const float*)d_in[0];
    const int*   ei     = (const int*)  d_in[1];
    const float* enc_w  = (const float*)d_in[2];
    const float* enc_b  = (const float*)d_in[3];
    const float* conv_w = (const float*)d_in[4];
    const float* conv_b = (const float*)d_in[5];
    const float* gg_w   = (const float*)d_in[6];
    const float* gg_b   = (const float*)d_in[7];
    const float* dec_w  = (const float*)d_in[8];
    const float* dec_b  = (const float*)d_in[9];
    float* out = (float*)d_out;

    float *pX, *pXd, *pA, *pXn, *pXG;
    cudaGetSymbolAddress((void**)&pX,  g_X);
    cudaGetSymbolAddress((void**)&pXd, g_Xd);
    cudaGetSymbolAddress((void**)&pA,  g_A);
    cudaGetSymbolAddress((void**)&pXn, g_Xn);
    cudaGetSymbolAddress((void**)&pXG, g_XG);

    // graph preprocessing (per-launch; deterministic)
    k_zero_counts<<<(NN + 255) / 256, 256>>>();
    k_count<<<(NE + 255) / 256, 256>>>(ei);
    k_scan_both<<<1, 1024>>>();
    k_fill<<<(NE + 255) / 256, 256>>>(ei);

    const int GEMM_BLOCKS = (NN + 31) / 32;
    const int NODE_BLOCKS = (NN * 16 + 255) / 256;

    // encoder: X = relu(x @ enc_w + enc_b); Xd = dis*X
    gemm_k<256, false, true><<<GEMM_BLOCKS, 128>>>(
        x, enc_w, nullptr, enc_b, nullptr, pX, nullptr, pXd);

    for (int it = 0; it < DEPTH; it++) {
        // shared aggregation for both convs
        k_agg<<<NODE_BLOCKS, 256>>>();
        // Xn = relu(A@conv_w + conv_b); XG = relu(A@gg_w + gg_b)
        gemm_k<64, true, false><<<GEMM_BLOCKS, 128>>>(
            pA, conv_w, gg_w, conv_b, gg_b, pXn, pXG, nullptr);
        // tau + state update
        k_gate<<<NODE_BLOCKS, 256>>>();
    }

    // decoder: out = relu(X @ dec_w + dec_b)
    gemm_k<64, false, false><<<GEMM_BLOCKS, 128>>>(
        pX, dec_w, nullptr, dec_b, nullptr, out, nullptr, nullptr);
}

// round 3
// speedup vs baseline: 1.3330x; 1.2293x over previous
#include <cuda_runtime.h>
#include <cuda_fp16.h>
#include <math.h>

#define NN 50000
#define NE 800000
#define DEPTH 4

// ---------------- scratch (static device globals; no allocation) ----------------
__device__ float  g_X  [NN*64];   // node state (fp32)
__device__ __half g_XdH[NN*64];   // dis[i]*X[i] as fp16 (gather stream, conv path)
__device__ float  g_A  [NN*64];   // aggregated features (shared by both convs)
__device__ float  g_Xn [NN*64];   // relu(conv(X))
__device__ __half g_XGH[NN*64];   // relu(gate-conv(X)) as fp16 (gather stream)
__device__ float g_dis[NN];
__device__ int g_cnt_dst[NN];
__device__ int g_cnt_src[NN];
__device__ int g_rp_dst[NN+1];
__device__ int g_rp_src[NN+1];
__device__ int g_off_dst[NN];
__device__ int g_off_src[NN];
__device__ int g_col_src[NE];   // CSR by dst: source node of each in-edge
__device__ int g_col_dst[NE];   // CSR by src: dest node of each out-edge

// ---------------- helpers ----------------
__device__ __forceinline__ float4 h4_to_f4(uint2 raw) {
    __half2 h0 = *reinterpret_cast<__half2*>(&raw.x);
    __half2 h1 = *reinterpret_cast<__half2*>(&raw.y);
    float2 f0 = __half22float2(h0);
    float2 f1 = __half22float2(h1);
    return make_float4(f0.x, f0.y, f1.x, f1.y);
}

__device__ __forceinline__ uint2 f4_to_h4(float4 v) {
    __half2 h0 = __floats2half2_rn(v.x, v.y);
    __half2 h1 = __floats2half2_rn(v.z, v.w);
    uint2 r;
    r.x = *reinterpret_cast<unsigned*>(&h0);
    r.y = *reinterpret_cast<unsigned*>(&h1);
    return r;
}

// ---------------- graph preprocessing ----------------
__global__ void k_zero_counts() {
    int i = blockIdx.x * blockDim.x + threadIdx.x;
    if (i < NN) { g_cnt_dst[i] = 0; g_cnt_src[i] = 0; }
}

__global__ void k_count(const int* __restrict__ ei) {
    int i = blockIdx.x * blockDim.x + threadIdx.x;
    if (i < NE) {
        int s = ei[i], d = ei[NE + i];
        atomicAdd(&g_cnt_dst[d], 1);
        atomicAdd(&g_cnt_src[s], 1);
    }
}

__device__ void scan_phase(const int* __restrict__ cnt, int* __restrict__ rp,
                           int* __restrict__ off, bool dodis, int* part) {
    int t = threadIdx.x;
    const int CH = (NN + 1023) / 1024;
    int b = t * CH;
    int e = b + CH; if (e > NN) e = NN; if (b > NN) b = NN;
    int s = 0;
    for (int i = b; i < e; i++) s += cnt[i];
    part[t] = s;
    __syncthreads();
    for (int o = 1; o < 1024; o <<= 1) {
        int v = (t >= o) ? part[t - o] : 0;
        __syncthreads();
        part[t] += v;
        __syncthreads();
    }
    int run = (t > 0) ? part[t - 1] : 0;
    for (int i = b; i < e; i++) {
        rp[i] = run; off[i] = run; run += cnt[i];
        if (dodis) g_dis[i] = rsqrtf((float)cnt[i] + 1.0f);
    }
    if (t == 1023) rp[NN] = part[1023];
}

__global__ void k_scan2() {
    __shared__ int part[1024];
    if (blockIdx.x == 0)
        scan_phase(g_cnt_dst, g_rp_dst, g_off_dst, true, part);
    else
        scan_phase(g_cnt_src, g_rp_src, g_off_src, false, part);
}

__global__ void k_fill(const int* __restrict__ ei) {
    int i = blockIdx.x * blockDim.x + threadIdx.x;
    if (i < NE) {
        int s = ei[i], d = ei[NE + i];
        int p = atomicAdd(&g_off_dst[d], 1); g_col_src[p] = s;
        int q = atomicAdd(&g_off_src[s], 1); g_col_dst[q] = d;
    }
}

// ---------------- GEMM: A[n x K] @ W[K x 64], tile 32 rows x 64 cols ----------------
// O1 = relu(A@W1 + b1)
// DUAL:         O2h = half(relu(A@W2 + b2))
// WRITE_SCALED: Osh = half(dis[row] * O1)
template<int K, bool DUAL, bool WRITE_SCALED>
__global__ void __launch_bounds__(128) gemm_k(
    const float* __restrict__ A,
    const float* __restrict__ W1,
    const float* __restrict__ W2,
    const float* __restrict__ b1,
    const float* __restrict__ b2,
    float* __restrict__ O1,
    __half* __restrict__ O2h,
    __half* __restrict__ Osh)
{
    __shared__ float AsT[64][36];
    constexpr int NW = DUAL ? 2 : 1;
    __shared__ float Ws[NW * 64 * 64];

    int tid = threadIdx.x;            // 128 threads
    int tx = tid & 15;                // 16 col-groups of 4
    int ty = tid >> 4;                // 8 row-groups of 4
    int rowbase = blockIdx.x * 32;
    int col0 = tx * 4;

    float acc1[4][4] = {};
    float acc2[4][4] = {};

    #pragma unroll
    for (int c = 0; c < K / 64; c++) {
        #pragma unroll
        for (int it = 0; it < 4; it++) {
            int i = tid + it * 128;
            int r = i >> 4, q = i & 15;
            int row = rowbase + r;
            float4 v = make_float4(0.f, 0.f, 0.f, 0.f);
            if (row < NN)
                v = *(const float4*)&A[(size_t)row * K + c * 64 + q * 4];
            AsT[q * 4 + 0][r] = v.x; AsT[q * 4 + 1][r] = v.y;
            AsT[q * 4 + 2][r] = v.z; AsT[q * 4 + 3][r] = v.w;
        }
        #pragma unroll
        for (int i = tid; i < NW * 64 * 16; i += 128) {
            float4 v = (i < 64 * 16)
                ? ((const float4*)(W1 + c * 64 * 64))[i]
                : ((const float4*)(W2 + c * 64 * 64))[i - 64 * 16];
            ((float4*)Ws)[i] = v;
        }
        __syncthreads();

        #pragma unroll 16
        for (int kk = 0; kk < 64; kk++) {
            float4 av = *(const float4*)&AsT[kk][ty * 4];
            float4 w1 = *(const float4*)&Ws[kk * 64 + col0];
            float a[4] = {av.x, av.y, av.z, av.w};
            #pragma unroll
            for (int i = 0; i < 4; i++) {
                acc1[i][0] += a[i] * w1.x;
                acc1[i][1] += a[i] * w1.y;
                acc1[i][2] += a[i] * w1.z;
                acc1[i][3] += a[i] * w1.w;
            }
            if (DUAL) {
                float4 w2 = *(const float4*)&Ws[64 * 64 + kk * 64 + col0];
                #pragma unroll
                for (int i = 0; i < 4; i++) {
                    acc2[i][0] += a[i] * w2.x;
                    acc2[i][1] += a[i] * w2.y;
                    acc2[i][2] += a[i] * w2.z;
                    acc2[i][3] += a[i] * w2.w;
                }
            }
        }
        __syncthreads();
    }

    float4 bb1 = *(const float4*)&b1[col0];
    float4 bb2 = DUAL ? *(const float4*)&b2[col0] : make_float4(0.f, 0.f, 0.f, 0.f);

    #pragma unroll
    for (int i = 0; i < 4; i++) {
        int row = rowbase + ty * 4 + i;
        if (row >= NN) break;
        float4 o;
        o.x = fmaxf(acc1[i][0] + bb1.x, 0.f);
        o.y = fmaxf(acc1[i][1] + bb1.y, 0.f);
        o.z = fmaxf(acc1[i][2] + bb1.z, 0.f);
        o.w = fmaxf(acc1[i][3] + bb1.w, 0.f);
        *(float4*)&O1[(size_t)row * 64 + col0] = o;
        if (WRITE_SCALED) {
            float s = g_dis[row];
            float4 os = make_float4(s * o.x, s * o.y, s * o.z, s * o.w);
            *(uint2*)&Osh[(size_t)row * 64 + col0] = f4_to_h4(os);
        }
        if (DUAL) {
            float4 o2;
            o2.x = fmaxf(acc2[i][0] + bb2.x, 0.f);
            o2.y = fmaxf(acc2[i][1] + bb2.y, 0.f);
            o2.z = fmaxf(acc2[i][2] + bb2.z, 0.f);
            o2.w = fmaxf(acc2[i][3] + bb2.w, 0.f);
            *(uint2*)&O2h[(size_t)row * 64 + col0] = f4_to_h4(o2);
        }
    }
}

// ---------------- shared aggregation over in-edges (CSR by dst) ----------------
// A[d] = dis[d] * ( dis[d]*X[d] + sum_{s->d} XdH[s] )
// 16 lanes per node, 4 features (8B fp16) per lane; 4-way pipelined edge loop
__global__ void __launch_bounds__(256) k_agg()
{
    int g = (blockIdx.x * blockDim.x + threadIdx.x) >> 4;
    int l = threadIdx.x & 15;
    if (g >= NN) return;
    int o = l * 4;

    float d = g_dis[g];
    float4 xs = *(const float4*)&g_X[(size_t)g * 64 + o];
    float4 a = make_float4(d * xs.x, d * xs.y, d * xs.z, d * xs.w);  // self-loop (fp32)

    int b = g_rp_dst[g], e = g_rp_dst[g + 1];
    int j = b;
    for (; j + 4 <= e; j += 4) {
        int s0 = g_col_src[j + 0];
        int s1 = g_col_src[j + 1];
        int s2 = g_col_src[j + 2];
        int s3 = g_col_src[j + 3];
        uint2 r0 = *(const uint2*)&g_XdH[(size_t)s0 * 64 + o];
        uint2 r1 = *(const uint2*)&g_XdH[(size_t)s1 * 64 + o];
        uint2 r2 = *(const uint2*)&g_XdH[(size_t)s2 * 64 + o];
        uint2 r3 = *(const uint2*)&g_XdH[(size_t)s3 * 64 + o];
        float4 v0 = h4_to_f4(r0), v1 = h4_to_f4(r1);
        float4 v2 = h4_to_f4(r2), v3 = h4_to_f4(r3);
        a.x += (v0.x + v1.x) + (v2.x + v3.x);
        a.y += (v0.y + v1.y) + (v2.y + v3.y);
        a.z += (v0.z + v1.z) + (v2.z + v3.z);
        a.w += (v0.w + v1.w) + (v2.w + v3.w);
    }
    for (; j < e; j++) {
        int s = g_col_src[j];
        float4 v = h4_to_f4(*(const uint2*)&g_XdH[(size_t)s * 64 + o]);
        a.x += v.x; a.y += v.y; a.z += v.z; a.w += v.w;
    }
    float4 r = make_float4(d * a.x, d * a.y, d * a.z, d * a.w);
    *(float4*)&g_A[(size_t)g * 64 + o] = r;
}

// ---------------- gate + state update (CSR by src) ----------------
// tau = tanh( sum_out (XG[s]-XG[d])^2 / max(outdeg,1) )
// X = X + tau*(Xn - X);  XdH = half(dis*X)
__global__ void __launch_bounds__(256) k_gate()
{
    int g = (blockIdx.x * blockDim.x + threadIdx.x) >> 4;
    int l = threadIdx.x & 15;
    if (g >= NN) return;
    int o = l * 4;

    float4 xs = h4_to_f4(*(const uint2*)&g_XGH[(size_t)g * 64 + o]);
    float4 s = make_float4(0.f, 0.f, 0.f, 0.f);
    int b = g_rp_src[g], e = g_rp_src[g + 1];
    int j = b;
    for (; j + 4 <= e; j += 4) {
        int d0 = g_col_dst[j + 0];
        int d1 = g_col_dst[j + 1];
        int d2 = g_col_dst[j + 2];
        int d3 = g_col_dst[j + 3];
        uint2 r0 = *(const uint2*)&g_XGH[(size_t)d0 * 64 + o];
        uint2 r1 = *(const uint2*)&g_XGH[(size_t)d1 * 64 + o];
        uint2 r2 = *(const uint2*)&g_XGH[(size_t)d2 * 64 + o];
        uint2 r3 = *(const uint2*)&g_XGH[(size_t)d3 * 64 + o];
        float4 v0 = h4_to_f4(r0), v1 = h4_to_f4(r1);
        float4 v2 = h4_to_f4(r2), v3 = h4_to_f4(r3);
        float t;
        t = xs.x - v0.x; s.x += t * t;  t = xs.y - v0.y; s.y += t * t;
        t = xs.z - v0.z; s.z += t * t;  t = xs.w - v0.w; s.w += t * t;
        t = xs.x - v1.x; s.x += t * t;  t = xs.y - v1.y; s.y += t * t;
        t = xs.z - v1.z; s.z += t * t;  t = xs.w - v1.w; s.w += t * t;
        t = xs.x - v2.x; s.x += t * t;  t = xs.y - v2.y; s.y += t * t;
        t = xs.z - v2.z; s.z += t * t;  t = xs.w - v2.w; s.w += t * t;
        t = xs.x - v3.x; s.x += t * t;  t = xs.y - v3.y; s.y += t * t;
        t = xs.z - v3.z; s.z += t * t;  t = xs.w - v3.w; s.w += t * t;
    }
    for (; j < e; j++) {
        int d = g_col_dst[j];
        float4 v = h4_to_f4(*(const uint2*)&g_XGH[(size_t)d * 64 + o]);
        float t;
        t = xs.x - v.x; s.x += t * t;  t = xs.y - v.y; s.y += t * t;
        t = xs.z - v.z; s.z += t * t;  t = xs.w - v.w; s.w += t * t;
    }
    float inv = 1.0f / fmaxf((float)(e - b), 1.f);
    float4 tau;
    tau.x = tanhf(s.x * inv); tau.y = tanhf(s.y * inv);
    tau.z = tanhf(s.z * inv); tau.w = tanhf(s.w * inv);

    float4 xo = *(const float4*)&g_X [(size_t)g * 64 + o];
    float4 xn = *(const float4*)&g_Xn[(size_t)g * 64 + o];
    float4 r;
    r.x = xo.x + tau.x * (xn.x - xo.x);
    r.y = xo.y + tau.y * (xn.y - xo.y);
    r.z = xo.z + tau.z * (xn.z - xo.z);
    r.w = xo.w + tau.w * (xn.w - xo.w);
    *(float4*)&g_X[(size_t)g * 64 + o] = r;
    float di = g_dis[g];
    float4 rd = make_float4(di * r.x, di * r.y, di * r.z, di * r.w);
    *(uint2*)&g_XdH[(size_t)g * 64 + o] = f4_to_h4(rd);
}

// ---------------- launch ----------------
extern "C" void kernel_launch(void* const* d_in, const int* in_sizes, int n_in,
                              void* d_out, int out_size)
{
    const float* x      = (const float*)d_in[0];
    const int*   ei     = (const int*)  d_in[1];
    const float* enc_w  = (const float*)d_in[2];
    const float* enc_b  = (const float*)d_in[3];
    const float* conv_w = (const float*)d_in[4];
    const float* conv_b = (const float*)d_in[5];
    const float* gg_w   = (const float*)d_in[6];
    const float* gg_b   = (const float*)d_in[7];
    const float* dec_w  = (const float*)d_in[8];
    const float* dec_b  = (const float*)d_in[9];
    float* out = (float*)d_out;

    float *pX, *pA, *pXn;
    __half *pXdH, *pXGH;
    cudaGetSymbolAddress((void**)&pX,   g_X);
    cudaGetSymbolAddress((void**)&pXdH, g_XdH);
    cudaGetSymbolAddress((void**)&pA,   g_A);
    cudaGetSymbolAddress((void**)&pXn,  g_Xn);
    cudaGetSymbolAddress((void**)&pXGH, g_XGH);

    // graph preprocessing (per-launch; deterministic)
    k_zero_counts<<<(NN + 255) / 256, 256>>>();
    k_count<<<(NE + 255) / 256, 256>>>(ei);
    k_scan2<<<2, 1024>>>();
    k_fill<<<(NE + 255) / 256, 256>>>(ei);

    const int GEMM_BLOCKS = (NN + 31) / 32;
    const int NODE_BLOCKS = (NN * 16 + 255) / 256;

    // encoder: X = relu(x @ enc_w + enc_b); XdH = half(dis*X)
    gemm_k<256, false, true><<<GEMM_BLOCKS, 128>>>(
        x, enc_w, nullptr, enc_b, nullptr, pX, nullptr, pXdH);

    for (int it = 0; it < DEPTH; it++) {
        k_agg<<<NODE_BLOCKS, 256>>>();
        gemm_k<64, true, false><<<GEMM_BLOCKS, 128>>>(
            pA, conv_w, gg_w, conv_b, gg_b, pXn, pXGH, nullptr);
        k_gate<<<NODE_BLOCKS, 256>>>();
    }

    // decoder: out = relu(X @ dec_w + dec_b)
    gemm_k<64, false, false><<<GEMM_BLOCKS, 128>>>(
        pX, dec_w, nullptr, dec_b, nullptr, out, nullptr, nullptr);
}